// round 2
// baseline (speedup 1.0000x reference)
#include <cuda_runtime.h>
#include <cstddef>

// SlideSum: out[b,j,f] = alpha * (x[b,i-1,f] + x[b,i,f] + x[b,i+1,f]),
// i = clamp(j, 1, L-2).  x: (64, 4096, 256) fp32. out same shape.
//
// R2: MLP=4 software pipeline (4 independent LDG.128 per group), T=32
// (read amplification 1.0625x), streaming stores (__stcs).

static constexpr int B   = 64;
static constexpr int L   = 4096;
static constexpr int F   = 256;
static constexpr int F4  = F / 4;                    // 64 float4 lanes per row
static constexpr int T   = 32;                       // L-rows per thread tile
static constexpr int TILES_PER_B = L / T;            // 128
static constexpr int UNITS_PER_BLOCK = 4;            // 4 (b,tile) units per 256-thread block
static constexpr int GRID = B * TILES_PER_B / UNITS_PER_BLOCK;  // 2048 blocks

__device__ __forceinline__ float4 win3(const float4 a, const float4 b,
                                       const float4 c, const float alpha) {
    float4 r;
    r.x = (a.x + b.x + c.x) * alpha;
    r.y = (a.y + b.y + c.y) * alpha;
    r.z = (a.z + b.z + c.z) * alpha;
    r.w = (a.w + b.w + c.w) * alpha;
    return r;
}

__global__ __launch_bounds__(256, 6)
void SlideSum_kernel(const float* __restrict__ x,
                     const float* __restrict__ alpha_p,
                     float* __restrict__ out) {
    const float alpha = __ldg(alpha_p);

    const int f4   = threadIdx.x & (F4 - 1);          // lane within row (coalesced)
    const int sub  = threadIdx.x >> 6;                // 0..3: unit within block
    const int unit = blockIdx.x * UNITS_PER_BLOCK + sub;
    const int b    = unit / TILES_PER_B;
    const int tile = unit % TILES_PER_B;
    const int j0   = tile * T;

    const size_t col_off = (size_t)b * L * F4 + f4;
    const float4* __restrict__ cx = reinterpret_cast<const float4*>(x) + col_off;
    float4* __restrict__       co = reinterpret_cast<float4*>(out) + col_off;

    if (j0 > 0 && j0 + T < L) {
        // Interior fast path: sliding window with MLP=4 load groups.
        float4 a  = cx[(size_t)(j0 - 1) * F4];
        float4 bb = cx[(size_t)j0 * F4];
#pragma unroll
        for (int g = 0; g < T; g += 4) {
            // 4 independent loads issued back-to-back (front-batched LDG.128).
            const float4 c0 = cx[(size_t)(j0 + g + 1) * F4];
            const float4 c1 = cx[(size_t)(j0 + g + 2) * F4];
            const float4 c2 = cx[(size_t)(j0 + g + 3) * F4];
            const float4 c3 = cx[(size_t)(j0 + g + 4) * F4];

            __stcs(&co[(size_t)(j0 + g + 0) * F4], win3(a,  bb, c0, alpha));
            __stcs(&co[(size_t)(j0 + g + 1) * F4], win3(bb, c0, c1, alpha));
            __stcs(&co[(size_t)(j0 + g + 2) * F4], win3(c0, c1, c2, alpha));
            __stcs(&co[(size_t)(j0 + g + 3) * F4], win3(c1, c2, c3, alpha));

            a  = c2;
            bb = c3;
        }
    } else {
        // Edge tiles (first and last tile of each column): clamped indices.
#pragma unroll 4
        for (int t = 0; t < T; ++t) {
            const int j = j0 + t;
            int i = j;
            if (i < 1)      i = 1;
            if (i > L - 2)  i = L - 2;
            const float4 a  = cx[(size_t)(i - 1) * F4];
            const float4 bb = cx[(size_t)i * F4];
            const float4 c  = cx[(size_t)(i + 1) * F4];
            __stcs(&co[(size_t)j * F4], win3(a, bb, c, alpha));
        }
    }
}

extern "C" void kernel_launch(void* const* d_in, const int* in_sizes, int n_in,
                              void* d_out, int out_size) {
    const float* x       = (const float*)d_in[0];
    const float* alpha_p = (const float*)d_in[1];
    float* out           = (float*)d_out;

    SlideSum_kernel<<<GRID, 256>>>(x, alpha_p, out);
}

// round 3
// speedup vs baseline: 1.1238x; 1.1238x over previous
#include <cuda_runtime.h>
#include <cstddef>

// SlideSum: out[b,j,f] = alpha * (x[b,i-1,f] + x[b,i,f] + x[b,i+1,f]),
// i = clamp(j, 1, L-2).  x: (64, 4096, 256) fp32. out same shape.
//
// R3: fine-grained CTAs (T=8 rows/unit, 64 KB r+w per CTA, grid=8192) to
// amortize launch ramp / drain / wave-quantization DRAM idle. occ-8 config
// (regs<=32) which matched R1's best. Streaming stores.

static constexpr int B   = 64;
static constexpr int L   = 4096;
static constexpr int F   = 256;
static constexpr int F4  = F / 4;                    // 64 float4 lanes per row
static constexpr int T   = 8;                        // L-rows per unit
static constexpr int TILES_PER_B = L / T;            // 512
static constexpr int UNITS_PER_BLOCK = 4;            // 4 units per 256-thread block
static constexpr int GRID = B * TILES_PER_B / UNITS_PER_BLOCK;  // 8192 blocks

__device__ __forceinline__ float4 win3(const float4 a, const float4 b,
                                       const float4 c, const float alpha) {
    float4 r;
    r.x = (a.x + b.x + c.x) * alpha;
    r.y = (a.y + b.y + c.y) * alpha;
    r.z = (a.z + b.z + c.z) * alpha;
    r.w = (a.w + b.w + c.w) * alpha;
    return r;
}

__global__ __launch_bounds__(256, 8)
void SlideSum_kernel(const float* __restrict__ x,
                     const float* __restrict__ alpha_p,
                     float* __restrict__ out) {
    const float alpha = __ldg(alpha_p);

    const int f4   = threadIdx.x & (F4 - 1);          // lane within row (coalesced)
    const int sub  = threadIdx.x >> 6;                // 0..3: unit within block
    const int unit = blockIdx.x * UNITS_PER_BLOCK + sub;
    const int b    = unit >> 9;                       // / TILES_PER_B (512)
    const int tile = unit & (TILES_PER_B - 1);
    const int j0   = tile * T;

    const size_t col_off = (size_t)b * L * F4 + f4;
    const float4* __restrict__ cx = reinterpret_cast<const float4*>(x) + col_off;
    float4* __restrict__       co = reinterpret_cast<float4*>(out) + col_off;

    if (j0 > 0 && j0 + T < L) {
        // Interior fast path: sliding window, T+2 loads for T outputs.
        float4 a  = cx[(size_t)(j0 - 1) * F4];
        float4 bb = cx[(size_t)j0 * F4];
#pragma unroll
        for (int t = 0; t < T; ++t) {
            const float4 c = cx[(size_t)(j0 + t + 1) * F4];
            __stcs(&co[(size_t)(j0 + t) * F4], win3(a, bb, c, alpha));
            a  = bb;
            bb = c;
        }
    } else {
        // Edge tiles (first and last tile of each column): clamped indices.
#pragma unroll
        for (int t = 0; t < T; ++t) {
            const int j = j0 + t;
            int i = j;
            if (i < 1)      i = 1;
            if (i > L - 2)  i = L - 2;
            const float4 a  = cx[(size_t)(i - 1) * F4];
            const float4 bb = cx[(size_t)i * F4];
            const float4 c  = cx[(size_t)(i + 1) * F4];
            __stcs(&co[(size_t)j * F4], win3(a, bb, c, alpha));
        }
    }
}

extern "C" void kernel_launch(void* const* d_in, const int* in_sizes, int n_in,
                              void* d_out, int out_size) {
    const float* x       = (const float*)d_in[0];
    const float* alpha_p = (const float*)d_in[1];
    float* out           = (float*)d_out;

    SlideSum_kernel<<<GRID, 256>>>(x, alpha_p, out);
}

// round 4
// speedup vs baseline: 1.1377x; 1.0123x over previous
#include <cuda_runtime.h>
#include <cstddef>

// SlideSum: out[b,j,f] = alpha * (x[b,i-1,f] + x[b,i,f] + x[b,i+1,f]),
// i = clamp(j, 1, L-2).  x: (64, 4096, 256) fp32. out same shape.
//
// R4: T=4 rows/unit (grid=16384, ~3us per CTA) to further amortize launch
// ramp / drain / wave-quantization DRAM idle. Cross-tile overlap reads are
// L2-absorbed (proven R1-R3: DRAM traffic pinned at unique-byte minimum).
// occ-8 config (regs<=32). Streaming stores.

static constexpr int B   = 64;
static constexpr int L   = 4096;
static constexpr int F   = 256;
static constexpr int F4  = F / 4;                    // 64 float4 lanes per row
static constexpr int T   = 4;                        // L-rows per unit
static constexpr int TILES_PER_B = L / T;            // 1024
static constexpr int UNITS_PER_BLOCK = 4;            // 4 units per 256-thread block
static constexpr int GRID = B * TILES_PER_B / UNITS_PER_BLOCK;  // 16384 blocks

__device__ __forceinline__ float4 win3(const float4 a, const float4 b,
                                       const float4 c, const float alpha) {
    float4 r;
    r.x = (a.x + b.x + c.x) * alpha;
    r.y = (a.y + b.y + c.y) * alpha;
    r.z = (a.z + b.z + c.z) * alpha;
    r.w = (a.w + b.w + c.w) * alpha;
    return r;
}

__global__ __launch_bounds__(256, 8)
void SlideSum_kernel(const float* __restrict__ x,
                     const float* __restrict__ alpha_p,
                     float* __restrict__ out) {
    const float alpha = __ldg(alpha_p);

    const int f4   = threadIdx.x & (F4 - 1);          // lane within row (coalesced)
    const int sub  = threadIdx.x >> 6;                // 0..3: unit within block
    const int unit = blockIdx.x * UNITS_PER_BLOCK + sub;
    const int b    = unit >> 10;                      // / TILES_PER_B (1024)
    const int tile = unit & (TILES_PER_B - 1);
    const int j0   = tile * T;

    const size_t col_off = (size_t)b * L * F4 + f4;
    const float4* __restrict__ cx = reinterpret_cast<const float4*>(x) + col_off;
    float4* __restrict__       co = reinterpret_cast<float4*>(out) + col_off;

    if (j0 > 0 && j0 + T < L) {
        // Interior fast path: sliding window, T+2 loads for T outputs.
        float4 a  = cx[(size_t)(j0 - 1) * F4];
        float4 bb = cx[(size_t)j0 * F4];
#pragma unroll
        for (int t = 0; t < T; ++t) {
            const float4 c = cx[(size_t)(j0 + t + 1) * F4];
            __stcs(&co[(size_t)(j0 + t) * F4], win3(a, bb, c, alpha));
            a  = bb;
            bb = c;
        }
    } else {
        // Edge tiles (first and last tile of each column): clamped indices.
#pragma unroll
        for (int t = 0; t < T; ++t) {
            const int j = j0 + t;
            int i = j;
            if (i < 1)      i = 1;
            if (i > L - 2)  i = L - 2;
            const float4 a  = cx[(size_t)(i - 1) * F4];
            const float4 bb = cx[(size_t)i * F4];
            const float4 c  = cx[(size_t)(i + 1) * F4];
            __stcs(&co[(size_t)j * F4], win3(a, bb, c, alpha));
        }
    }
}

extern "C" void kernel_launch(void* const* d_in, const int* in_sizes, int n_in,
                              void* d_out, int out_size) {
    const float* x       = (const float*)d_in[0];
    const float* alpha_p = (const float*)d_in[1];
    float* out           = (float*)d_out;

    SlideSum_kernel<<<GRID, 256>>>(x, alpha_p, out);
}